// round 8
// baseline (speedup 1.0000x reference)
#include <cuda_runtime.h>

#define DN 32
#define DE 16
#define DH 64
#define DO 32

// Precomputed per-node x@W1[:32,:] + b1  (100000 x 64 f32 = 25.6 MB, L2-resident)
__device__ __align__(16) float g_pre[100000 * DH];
__device__ int g_which;  // which candidate buffer is edge_index (0 = A, 1 = B)
__device__ int g_is64;   // 1 if edge_index is int64, 0 if int32

using u64 = unsigned long long;

__device__ __forceinline__ u64 pk(float lo, float hi) {
  u64 r; asm("mov.b64 %0,{%1,%2};" : "=l"(r) : "f"(lo), "f"(hi)); return r;
}
__device__ __forceinline__ void upk(u64 v, float& lo, float& hi) {
  asm("mov.b64 {%0,%1},%2;" : "=f"(lo), "=f"(hi) : "l"(v));
}
__device__ __forceinline__ u64 fma2(u64 a, u64 b, u64 c) {
  u64 d; asm("fma.rn.f32x2 %0,%1,%2,%3;" : "=l"(d) : "l"(a), "l"(b), "l"(c)); return d;
}
__device__ __forceinline__ void red1(float* p, float v) {
  asm volatile("red.global.add.f32 [%0], %1;" :: "l"(p), "f"(v) : "memory");
}

__global__ void zero_out(float4* __restrict__ out, int n4) {
  int i = blockIdx.x * blockDim.x + threadIdx.x;
  if (i < n4) out[i] = make_float4(0.f, 0.f, 0.f, 0.f);
}

// One warp classifies the two size-ambiguous buffers (parallel, ~2 rounds of loads).
__global__ void detect(const unsigned* __restrict__ A,
                       const unsigned* __restrict__ B, unsigned n_nodes) {
  const unsigned* c[2] = {A, B};
  int l = threadIdx.x;
  int which = 1, is64 = 1;  // fallback: dict order (A=x, B=edge_index int64)
  for (int cand = 0; cand < 2; cand++) {
    bool small = true, oddz = true;
    for (int i = l; i < 2048; i += 32) {
      unsigned v = c[cand][i];
      if (v >= n_nodes) small = false;
      if ((i & 1) && v != 0u) oddz = false;
    }
    bool all_small = __all_sync(0xffffffffu, small);
    bool all_oddz  = __all_sync(0xffffffffu, oddz);
    if (all_small) { which = cand; is64 = all_oddz ? 1 : 0; break; }
  }
  if (l == 0) { g_which = which; g_is64 = is64; }
}

// 4 nodes per 256-thread block; thread j of each 64-group computes pre[node][j].
__global__ __launch_bounds__(256) void precompute(
    const float* __restrict__ candA, const float* __restrict__ candB,
    const float* __restrict__ W1, const float* __restrict__ b1, int n_nodes) {
  __shared__ __align__(16) float sW[DN * DH];
  __shared__ float sb[DH];
  int t = threadIdx.x;
  for (int i = t; i < DN * DH; i += 256) sW[i] = W1[i];  // W1 rows 0..31
  if (t < DH) sb[t] = b1[t];
  __syncthreads();
  const float* x = (g_which == 0) ? candB : candA;  // x = the non-index buffer
  int node = blockIdx.x * 4 + (t >> 6);
  if (node >= n_nodes) return;
  int j = t & 63;
  const float* xr = x + node * DN;
  float acc = sb[j];
#pragma unroll
  for (int i = 0; i < DN; i++) acc = fmaf(__ldg(xr + i), sW[i * DH + j], acc);
  g_pre[node * DH + j] = acc;
}

// Warp-cooperative edge MLP. One warp processes 32 consecutive edges, one edge
// per iteration. Lane j: computes h[2j],h[2j+1] (layer 1), owns output dim j
// (layer 2). All weights in registers as f32x2 pairs packed over the reduction
// dim; gather/scatter fully coalesced; h broadcast through a smem ping-pong.
__global__ __launch_bounds__(256) void edge_mlp(
    const void* __restrict__ candA, const void* __restrict__ candB,
    const float* __restrict__ ea, const float* __restrict__ W1,
    const float* __restrict__ W2, const float* __restrict__ b2,
    float* __restrict__ out, int E, unsigned n_nodes) {
  __shared__ __align__(16) float sh[8][2][DH];  // per-warp ping-pong h staging (4 KB)
  const int t = threadIdx.x, w = t >> 5, j = t & 31;
  const int is64 = g_is64;
  const void* eip = (g_which == 0) ? candA : candB;

  // ---- one-time per-lane weight pack (coalesced LDG, L1/L2-hot) ----
  u64 w1p0[8], w1p1[8], w2p[32];
  const int d0 = 2 * j, d1 = 2 * j + 1;
#pragma unroll
  for (int i = 0; i < 8; i++) {
    w1p0[i] = pk(W1[(DN + 2 * i) * DH + d0], W1[(DN + 2 * i + 1) * DH + d0]);
    w1p1[i] = pk(W1[(DN + 2 * i) * DH + d1], W1[(DN + 2 * i + 1) * DH + d1]);
  }
#pragma unroll
  for (int m = 0; m < 32; m++)
    w2p[m] = pk(W2[(2 * m) * DO + j], W2[(2 * m + 1) * DO + j]);
  const float b2j = b2[j];

  const long long ebase = ((long long)blockIdx.x * 8 + w) * 32;
  if (ebase >= E) return;
  const int rmax = (E - ebase >= 32) ? 32 : (int)(E - ebase);

  // index loader (uniform across warp), clamped for safety
  auto load_idx = [&](long long e, unsigned& row, unsigned& col) {
    if (is64) {
      const long long* p = (const long long*)eip;
      row = (unsigned)p[e]; col = (unsigned)p[(long long)E + e];
    } else {
      const int* p = (const int*)eip;
      row = (unsigned)p[e]; col = (unsigned)p[(long long)E + e];
    }
    if (row >= n_nodes) row = 0;
    if (col >= n_nodes) col = 0;
  };

  // prefetch edge 0: indices + coalesced gather of pre pair
  unsigned row_c, col_c;
  load_idx(ebase, row_c, col_c);
  float2 pre_c = __ldg((const float2*)(g_pre + (size_t)col_c * DH) + j);

  int buf = 0;
  for (int r = 0; r < rmax; r++) {
    const long long e = ebase + r;

    // software-pipeline: prefetch next edge's indices + gather
    unsigned row_n = 0, col_n = 0;
    float2 pre_n = make_float2(0.f, 0.f);
    if (r + 1 < rmax) {
      load_idx(e + 1, row_n, col_n);
      pre_n = __ldg((const float2*)(g_pre + (size_t)col_n * DH) + j);
    }

    // edge features: uniform LDG.128 x4 (1 line each, L1-hot within the batch)
    const ulonglong2* eap = (const ulonglong2*)(ea + (size_t)e * DE);
    ulonglong2 u0 = __ldg(eap + 0), u1 = __ldg(eap + 1);
    ulonglong2 u2 = __ldg(eap + 2), u3 = __ldg(eap + 3);
    u64 ap[8] = {u0.x, u0.y, u1.x, u1.y, u2.x, u2.y, u3.x, u3.y};

    // layer 1: h[d0], h[d1] via packed FMA over i-pairs; seed with pre
    u64 acc0 = pk(pre_c.x, 0.f), acc1 = pk(pre_c.y, 0.f);
#pragma unroll
    for (int i = 0; i < 8; i++) {
      acc0 = fma2(ap[i], w1p0[i], acc0);
      acc1 = fma2(ap[i], w1p1[i], acc1);
    }
    float l0, h0, l1, h1;
    upk(acc0, l0, h0); upk(acc1, l1, h1);
    float hA = fmaxf(l0 + h0, 0.f), hB = fmaxf(l1 + h1, 0.f);

    // stage h to smem (STS.64, conflict-free), broadcast back for layer 2
    ((float2*)sh[w][buf])[j] = make_float2(hA, hB);
    __syncwarp();

    // layer 2: o_j = b2_j + sum_k h_k * W2[k][j], packed over k-pairs
    u64 acc = pk(b2j, 0.f);
    const ulonglong2* hp = (const ulonglong2*)sh[w][buf];
#pragma unroll
    for (int q = 0; q < 16; q++) {
      ulonglong2 hv = hp[q];               // broadcast LDS.128: pairs 2q, 2q+1
      acc = fma2(hv.x, w2p[2 * q], acc);
      acc = fma2(hv.y, w2p[2 * q + 1], acc);
    }
    float lo, hi;
    upk(acc, lo, hi);

    // coalesced scatter: whole warp hits one 128B line
    red1(out + (size_t)row_c * DO + j, lo + hi);

    buf ^= 1;  // ping-pong; the per-iteration syncwarp orders reuse 2 iters later
    row_c = row_n; col_c = col_n; pre_c = pre_n;
  }
}

extern "C" void kernel_launch(void* const* d_in, const int* in_sizes, int n_in,
                              void* d_out, int out_size) {
  // Identify inputs by element count; only x vs edge_index is ambiguous.
  int iW1 = 3, ib1 = 4, iW2 = 5, ib2 = 6;     // dict-order defaults
  int big[3], nbig = 0;
  for (int i = 0; i < n_in; i++) {
    int s = in_sizes[i];
    if      (s == (DN + DE) * DH) iW1 = i;
    else if (s == DH)             ib1 = i;
    else if (s == DH * DO)        iW2 = i;
    else if (s == DO)             ib2 = i;
    else if (nbig < 3)            big[nbig++] = i;
  }
  // Largest remaining buffer = edge_attr; the other two = {x, edge_index}.
  int iea = big[0];
  for (int k = 1; k < nbig; k++)
    if (in_sizes[big[k]] > in_sizes[iea]) iea = big[k];
  int cA = -1, cB = -1;
  for (int k = 0; k < nbig; k++) {
    if (big[k] == iea) continue;
    if (cA < 0) cA = big[k]; else cB = big[k];
  }

  const float* ea = (const float*)d_in[iea];
  const float* W1 = (const float*)d_in[iW1];
  const float* b1 = (const float*)d_in[ib1];
  const float* W2 = (const float*)d_in[iW2];
  const float* b2 = (const float*)d_in[ib2];
  float* out = (float*)d_out;

  int E = in_sizes[iea] / DE;                 // 1,600,000
  int N = in_sizes[cA] / DN;                  // 100,000 (both candidates: 3.2M elems)

  detect<<<1, 32>>>((const unsigned*)d_in[cA], (const unsigned*)d_in[cB], (unsigned)N);
  int n4 = out_size / 4;
  zero_out<<<(n4 + 255) / 256, 256>>>((float4*)out, n4);
  precompute<<<(N + 3) / 4, 256>>>((const float*)d_in[cA], (const float*)d_in[cB],
                                   W1, b1, N);
  edge_mlp<<<(E + 255) / 256, 256>>>(d_in[cA], d_in[cB], ea, W1, W2, b2, out, E,
                                     (unsigned)N);
}

// round 14
// speedup vs baseline: 2.9378x; 2.9378x over previous
#include <cuda_runtime.h>
#include <cstdint>

#define DN 32
#define DE 16
#define DH 64
#define DO 32

// Precomputed per-node x@W1[:32,:] + b1  (100000 x 64 f32 = 25.6 MB, L2-resident)
__device__ __align__(16) float g_pre[100000 * DH];
__device__ int g_which;  // which candidate buffer is edge_index (0 = A, 1 = B)
__device__ int g_is64;   // 1 if edge_index is int64, 0 if int32

using u64 = unsigned long long;

__device__ __forceinline__ u64 pk2(float a) {  // duplicate scalar into both lanes
  u64 r; asm("mov.b64 %0,{%1,%1};" : "=l"(r) : "f"(a)); return r;
}
__device__ __forceinline__ void upk(u64 v, float& lo, float& hi) {
  asm("mov.b64 {%0,%1},%2;" : "=f"(lo), "=f"(hi) : "l"(v));
}
__device__ __forceinline__ u64 fma2(u64 a, u64 b, u64 c) {
  u64 d; asm("fma.rn.f32x2 %0,%1,%2,%3;" : "=l"(d) : "l"(a), "l"(b), "l"(c)); return d;
}
__device__ __forceinline__ void red1(float* p, float v) {
  asm volatile("red.global.add.f32 [%0], %1;" :: "l"(p), "f"(v) : "memory");
}

__global__ void zero_out(float4* __restrict__ out, int n4) {
  int i = blockIdx.x * blockDim.x + threadIdx.x;
  if (i < n4) out[i] = make_float4(0.f, 0.f, 0.f, 0.f);
}

// One warp classifies the two size-ambiguous buffers.
__global__ void detect(const unsigned* __restrict__ A,
                       const unsigned* __restrict__ B, unsigned n_nodes) {
  const unsigned* c[2] = {A, B};
  int l = threadIdx.x;
  int which = 1, is64 = 1;  // fallback: dict order (A=x, B=edge_index int64)
  for (int cand = 0; cand < 2; cand++) {
    bool small = true, oddz = true;
    for (int i = l; i < 512; i += 32) {
      unsigned v = c[cand][i];
      if (v >= n_nodes) small = false;
      if ((i & 1) && v != 0u) oddz = false;
    }
    bool all_small = __all_sync(0xffffffffu, small);
    bool all_oddz = __all_sync(0xffffffffu, oddz);
    if (all_small) { which = cand; is64 = all_oddz ? 1 : 0; break; }
  }
  if (l == 0) { g_which = which; g_is64 = is64; }
}

// 4 nodes per 256-thread block; thread j of each 64-group computes pre[node][j].
__global__ __launch_bounds__(256) void precompute(
    const float* __restrict__ candA, const float* __restrict__ candB,
    const float* __restrict__ W1, const float* __restrict__ b1, int n_nodes) {
  __shared__ __align__(16) float sW[DN * DH];
  __shared__ float sb[DH];
  int t = threadIdx.x;
  for (int i = t; i < DN * DH; i += 256) sW[i] = W1[i];  // W1 rows 0..31
  if (t < DH) sb[t] = b1[t];
  __syncthreads();
  const float* x = (g_which == 0) ? candB : candA;  // x = the non-index buffer
  int node = blockIdx.x * 4 + (t >> 6);
  if (node >= n_nodes) return;
  int j = t & 63;
  const float* xr = x + node * DN;
  float acc = sb[j];
#pragma unroll
  for (int i = 0; i < DN; i++) acc = fmaf(__ldg(xr + i), sW[i * DH + j], acc);
  g_pre[node * DH + j] = acc;
}

// Per-thread edge MLP with warp-staged gather/scatter and packed f32x2 FMA.
// Each warp owns 32 consecutive edges; thread = edge. The pre[col] rows are
// cooperatively loaded (coalesced) into a swizzled smem region, read back at
// the LDS structural minimum, and the same region is reused to transpose the
// outputs so the scatter is one 128B line per edge.
__global__ __launch_bounds__(128) void edge_mlp(
    const void* __restrict__ candA, const void* __restrict__ candB,
    const float* __restrict__ ea, const float* __restrict__ W1,
    const float* __restrict__ W2, const float* __restrict__ b2,
    float* __restrict__ out, int E, unsigned n_nodes) {
  __shared__ __align__(16) float s_stage[4][32 * DH];  // 32 KB: pre rows / o transpose
  __shared__ __align__(16) float sW1b[DE * DH];        // 4 KB
  __shared__ __align__(16) float sW2[DH * DO];         // 8 KB
  __shared__ __align__(16) float sb2[DO];
  const int t = threadIdx.x, w = t >> 5, l = t & 31;

  for (int i = t; i < DE * DH; i += 128) sW1b[i] = W1[DN * DH + i];
  for (int i = t; i < DH * DO; i += 128) sW2[i] = W2[i];
  if (t < DO) sb2[t] = b2[t];
  __syncthreads();

  const int is64 = g_is64;
  const void* eip = (g_which == 0) ? candA : candB;
  const long long eb = ((long long)blockIdx.x * 4 + w) * 32;
  const long long e = eb + l;
  const bool valid = e < E;

  unsigned row = 0, col = 0;
  if (valid) {
    if (is64) {
      const long long* p = (const long long*)eip;
      row = (unsigned)p[e]; col = (unsigned)p[(long long)E + e];
    } else {
      const int* p = (const int*)eip;
      row = (unsigned)p[e]; col = (unsigned)p[(long long)E + e];
    }
    if (row >= n_nodes) row = 0;
    if (col >= n_nodes) col = 0;
  }

  // ---- cooperative gather: 32 pre rows -> swizzled smem (coalesced LDG) ----
  float* stg = s_stage[w];
  {
    const int c = l & 15;          // 16B chunk within row
#pragma unroll
    for (int it = 0; it < 16; it++) {
      const int r = 2 * it + (l >> 4);
      const unsigned colr = __shfl_sync(0xffffffffu, col, r);
      uint4 v = __ldg((const uint4*)(g_pre + (size_t)colr * DH) + c);
      const int pc = c ^ (r & 15);  // chunk swizzle: distinct banks across rows
      *(uint4*)(stg + r * DH + pc * 4) = v;
    }
  }
  __syncwarp();

  // ---- edge features (per-thread, 4 LDG.128) ----
  float a[DE];
  {
    const float4* ep = (const float4*)(ea + (size_t)(valid ? e : 0) * DE);
#pragma unroll
    for (int q = 0; q < DE / 4; q++) {
      float4 v = __ldg(ep + q);
      a[4*q] = v.x; a[4*q+1] = v.y; a[4*q+2] = v.z; a[4*q+3] = v.w;
    }
  }

  // ---- seed h from own staged row (swizzled reads, structural-min LDS) ----
  u64 h2[DH / 2];
#pragma unroll
  for (int c = 0; c < 16; c++) {
    const int pc = c ^ (l & 15);
    ulonglong2 v = *(const ulonglong2*)(stg + l * DH + pc * 4);
    h2[2*c] = v.x; h2[2*c+1] = v.y;
  }

  // ---- layer 1: h += ea @ W1b  (packed f32x2: 512 fma2 + 256 LDS.128) ----
#pragma unroll
  for (int i = 0; i < DE; i++) {
    const u64 ai2 = pk2(a[i]);
    const ulonglong2* wr = (const ulonglong2*)(sW1b + i * DH);
#pragma unroll
    for (int q = 0; q < 16; q++) {
      ulonglong2 wv = wr[q];
      h2[2*q]   = fma2(ai2, wv.x, h2[2*q]);
      h2[2*q+1] = fma2(ai2, wv.y, h2[2*q+1]);
    }
  }

  // ---- relu ----
  float hr[DH];
#pragma unroll
  for (int j = 0; j < DH / 2; j++) {
    float f0, f1;
    upk(h2[j], f0, f1);
    hr[2*j] = fmaxf(f0, 0.f);
    hr[2*j+1] = fmaxf(f1, 0.f);
  }

  // ---- layer 2: o = b2 + relu(h) @ W2  (1024 fma2 + 512 LDS.128) ----
  u64 o2[DO / 2];
  {
    const ulonglong2* bp = (const ulonglong2*)sb2;
#pragma unroll
    for (int q = 0; q < 8; q++) {
      ulonglong2 v = bp[q];
      o2[2*q] = v.x; o2[2*q+1] = v.y;
    }
  }
#pragma unroll
  for (int k = 0; k < DH; k++) {
    const u64 hk2 = pk2(hr[k]);
    const ulonglong2* wr = (const ulonglong2*)(sW2 + k * DO);
#pragma unroll
    for (int q = 0; q < 8; q++) {
      ulonglong2 wv = wr[q];
      o2[2*q]   = fma2(hk2, wv.x, o2[2*q]);
      o2[2*q+1] = fma2(hk2, wv.y, o2[2*q+1]);
    }
  }

  // ---- staged scatter: transpose o through smem, 1 coalesced RED line/edge ----
  __syncwarp();  // all pre-row reads done; reuse the stage region
#pragma unroll
  for (int c = 0; c < 8; c++) {
    const int pc = c ^ (l & 7);
    ulonglong2 v; v.x = o2[2*c]; v.y = o2[2*c+1];
    *(ulonglong2*)(stg + l * DO + pc * 4) = v;
  }
  __syncwarp();
  {
    const int c = l >> 2, wi = l & 3;
#pragma unroll
    for (int e2 = 0; e2 < 32; e2++) {
      if (eb + e2 >= E) break;
      const unsigned rowe = __shfl_sync(0xffffffffu, row, e2);
      const int pc = c ^ (e2 & 7);
      float v = stg[e2 * DO + pc * 4 + wi];
      red1(out + (size_t)rowe * DO + l, v);
    }
  }
}

extern "C" void kernel_launch(void* const* d_in, const int* in_sizes, int n_in,
                              void* d_out, int out_size) {
  // Identify inputs by element count; only x vs edge_index is ambiguous.
  int iW1 = 3, ib1 = 4, iW2 = 5, ib2 = 6;     // dict-order defaults
  int big[3], nbig = 0;
  for (int i = 0; i < n_in; i++) {
    int s = in_sizes[i];
    if      (s == (DN + DE) * DH) iW1 = i;
    else if (s == DH)             ib1 = i;
    else if (s == DH * DO)        iW2 = i;
    else if (s == DO)             ib2 = i;
    else if (nbig < 3)            big[nbig++] = i;
  }
  int iea = big[0];
  for (int k = 1; k < nbig; k++)
    if (in_sizes[big[k]] > in_sizes[iea]) iea = big[k];
  int cA = -1, cB = -1;
  for (int k = 0; k < nbig; k++) {
    if (big[k] == iea) continue;
    if (cA < 0) cA = big[k]; else cB = big[k];
  }

  const float* ea = (const float*)d_in[iea];
  const float* W1 = (const float*)d_in[iW1];
  const float* b1 = (const float*)d_in[ib1];
  const float* W2 = (const float*)d_in[iW2];
  const float* b2 = (const float*)d_in[ib2];
  float* out = (float*)d_out;

  int E = in_sizes[iea] / DE;                 // 1,600,000
  int N = in_sizes[cA] / DN;                  // 100,000

  detect<<<1, 32>>>((const unsigned*)d_in[cA], (const unsigned*)d_in[cB], (unsigned)N);
  int n4 = out_size / 4;
  zero_out<<<(n4 + 255) / 256, 256>>>((float4*)out, n4);
  precompute<<<(N + 3) / 4, 256>>>((const float*)d_in[cA], (const float*)d_in[cB],
                                   W1, b1, N);
  edge_mlp<<<(E + 127) / 128, 128>>>(d_in[cA], d_in[cB], ea, W1, W2, b2, out, E,
                                     (unsigned)N);
}

// round 17
// speedup vs baseline: 9.0197x; 3.0702x over previous
#include <cuda_runtime.h>
#include <cuda_fp16.h>
#include <cstdint>

#define DN 32
#define DE 16
#define DH 64
#define DO 32
#define STRIDE 68   // stage row stride in floats (68*4B: rotates banks per row)

__device__ int g_which;  // which candidate buffer is edge_index (0 = A, 1 = B)
__device__ int g_is64;   // 1 if edge_index is int64, 0 if int32

using u64 = unsigned long long;

// split f32 pair into fp16 hi + fp16 residual(lo), packed half2
__device__ __forceinline__ void split2(float f0, float f1, uint32_t& hi, uint32_t& lo) {
  __half2 h = __floats2half2_rn(f0, f1);
  float2 b = __half22float2(h);
  __half2 l = __floats2half2_rn(f0 - b.x, f1 - b.y);
  hi = *(uint32_t*)&h;
  lo = *(uint32_t*)&l;
}

__device__ __forceinline__ void mma16816(float* c, const uint32_t* a,
                                         uint32_t b0, uint32_t b1) {
  asm volatile(
      "mma.sync.aligned.m16n8k16.row.col.f32.f16.f16.f32 "
      "{%0,%1,%2,%3},{%4,%5,%6,%7},{%8,%9},{%0,%1,%2,%3};"
      : "+f"(c[0]), "+f"(c[1]), "+f"(c[2]), "+f"(c[3])
      : "r"(a[0]), "r"(a[1]), "r"(a[2]), "r"(a[3]), "r"(b0), "r"(b1));
}

__device__ __forceinline__ void red2(float* p, float a, float b) {
  asm volatile("red.global.v2.f32.add [%0], {%1,%2};"
               :: "l"(p), "f"(a), "f"(b) : "memory");
}

__global__ void zero_out(float4* __restrict__ out, int n4) {
  int i = blockIdx.x * blockDim.x + threadIdx.x;
  if (i < n4) out[i] = make_float4(0.f, 0.f, 0.f, 0.f);
}

// One warp classifies the two size-ambiguous buffers.
__global__ void detect(const unsigned* __restrict__ A,
                       const unsigned* __restrict__ B, unsigned n_nodes) {
  const unsigned* c[2] = {A, B};
  int l = threadIdx.x;
  int which = 1, is64 = 1;  // fallback: dict order (A=x, B=edge_index int64)
  for (int cand = 0; cand < 2; cand++) {
    bool small = true, oddz = true;
    for (int i = l; i < 512; i += 32) {
      unsigned v = c[cand][i];
      if (v >= n_nodes) small = false;
      if ((i & 1) && v != 0u) oddz = false;
    }
    bool all_small = __all_sync(0xffffffffu, small);
    bool all_oddz = __all_sync(0xffffffffu, oddz);
    if (all_small) { which = cand; is64 = all_oddz ? 1 : 0; break; }
  }
  if (l == 0) { g_which = which; g_is64 = is64; }
}

// Tensor-core edge MLP. One warp = one batch of 32 edges per iteration.
//   A1[32x48] = [x[col] || ea] (fp16 hi/lo)  -> C1 = A1@W1 + b1  (mma, f32 acc)
//   C1 frags --relu+split--> A2 frags (in-register; C(m16n8) == A(m16k16) layout)
//   C2 = A2@W2 + b2  -> red.v2 scatter straight from fragments.
// 3-product split (ah*bh + al*bh + ah*bl) keeps fp32-level accuracy.
__global__ __launch_bounds__(128) void edge_mma(
    const void* __restrict__ candA, const void* __restrict__ candB,
    const float* __restrict__ ea, const float* __restrict__ W1,
    const float* __restrict__ b1, const float* __restrict__ W2,
    const float* __restrict__ b2, float* __restrict__ out,
    int E, unsigned n_nodes) {
  __shared__ float sA[4][32 * STRIDE];              // per-warp A1 stage (f32)
  __shared__ u64 sW1f[2][24][32];                   // [hi/lo][nt*3+kt][lane]
  const int tid = threadIdx.x, w = tid >> 5, l = tid & 31;
  const int lq = l >> 2, lr = l & 3;                // groupID, threadID-in-group

  const int is64 = g_is64;
  const void* eip = (g_which == 0) ? candA : candB;
  const float* x = (const float*)((g_which == 0) ? candB : candA);

  // ---- block init: W1 B-fragments, pre-arranged [frag][lane] ----
  for (int idx = tid; idx < 24 * 32; idx += 128) {
    int f = idx >> 5, ll = idx & 31;
    int kt = f % 3, nt = f / 3;
    int k0 = kt * 16 + 2 * (ll & 3), n = nt * 8 + (ll >> 2);
    uint32_t h0, l0, h1, l1;
    split2(W1[k0 * DH + n], W1[(k0 + 1) * DH + n], h0, l0);
    split2(W1[(k0 + 8) * DH + n], W1[(k0 + 9) * DH + n], h1, l1);
    sW1f[0][f][ll] = (u64)h0 | ((u64)h1 << 32);
    sW1f[1][f][ll] = (u64)l0 | ((u64)l1 << 32);
  }

  // ---- per-warp register fragments: W2 (hi/lo), b1, b2 ----
  uint32_t w2h[4][4][2], w2l[4][4][2];
#pragma unroll
  for (int kt = 0; kt < 4; kt++)
#pragma unroll
    for (int nt = 0; nt < 4; nt++) {
      int k0 = kt * 16 + 2 * lr, n = nt * 8 + lq;
      split2(W2[k0 * DO + n], W2[(k0 + 1) * DO + n], w2h[kt][nt][0], w2l[kt][nt][0]);
      split2(W2[(k0 + 8) * DO + n], W2[(k0 + 9) * DO + n], w2h[kt][nt][1], w2l[kt][nt][1]);
    }
  float b1f[8][2], b2f[4][2];
#pragma unroll
  for (int nt = 0; nt < 8; nt++) {
    b1f[nt][0] = __ldg(b1 + nt * 8 + 2 * lr);
    b1f[nt][1] = __ldg(b1 + nt * 8 + 2 * lr + 1);
  }
#pragma unroll
  for (int nt = 0; nt < 4; nt++) {
    b2f[nt][0] = __ldg(b2 + nt * 8 + 2 * lr);
    b2f[nt][1] = __ldg(b2 + nt * 8 + 2 * lr + 1);
  }
  __syncthreads();

  float* stg = sA[w];
  const int NB = (E + 31) / 32;
  const int gw = blockIdx.x * 4 + w, TW = gridDim.x * 4;

  for (int batch = gw; batch < NB; batch += TW) {
    const long long eb = (long long)batch * 32;
    const long long e = eb + l;
    const bool valid = e < E;

    // per-lane edge indices (lane l <-> edge l of the batch)
    unsigned row = 0, col = 0;
    if (valid) {
      if (is64) {
        const long long* p = (const long long*)eip;
        row = (unsigned)p[e]; col = (unsigned)p[(long long)E + e];
      } else {
        const int* p = (const int*)eip;
        row = (unsigned)p[e]; col = (unsigned)p[(long long)E + e];
      }
      if (row >= n_nodes) row = 0;
      if (col >= n_nodes) col = 0;
    }

    __syncwarp();  // previous batch's stage reads complete before overwrite

    // ---- stage x[col] rows (coalesced: 4 rows x 8 chunks per instr) ----
#pragma unroll
    for (int it = 0; it < 8; it++) {
      const int r = 4 * it + (l >> 3), c = l & 7;
      const unsigned colr = __shfl_sync(0xffffffffu, col, r);
      float4 v = __ldg((const float4*)(x + (size_t)colr * DN) + c);
      *(float4*)(stg + r * STRIDE + c * 4) = v;
    }
    // ---- stage ea rows (coalesced: 8 rows x 4 chunks per instr) ----
#pragma unroll
    for (int it = 0; it < 4; it++) {
      const int rr = 8 * it + (l >> 2), c = l & 3;
      long long ee = eb + rr; if (ee >= E) ee = E - 1;
      float4 v = __ldg((const float4*)(ea + ee * DE) + c);
      *(float4*)(stg + rr * STRIDE + DN + c * 4) = v;
    }
    __syncwarp();

    // ---- layer 1: C1[2m][8n] = A1 @ W1 + b1 ----
    float c1[2][8][4];
#pragma unroll
    for (int mt = 0; mt < 2; mt++)
#pragma unroll
      for (int nt = 0; nt < 8; nt++) {
        c1[mt][nt][0] = b1f[nt][0]; c1[mt][nt][1] = b1f[nt][1];
        c1[mt][nt][2] = b1f[nt][0]; c1[mt][nt][3] = b1f[nt][1];
      }
#pragma unroll
    for (int kt = 0; kt < 3; kt++) {
      uint32_t ah[2][4], al[2][4];
      const int k0 = kt * 16 + 2 * lr;
#pragma unroll
      for (int mt = 0; mt < 2; mt++) {
        const int rb = mt * 16 + lq;
        float2 p0 = *(float2*)(stg + rb * STRIDE + k0);
        float2 p1 = *(float2*)(stg + (rb + 8) * STRIDE + k0);
        float2 p2 = *(float2*)(stg + rb * STRIDE + k0 + 8);
        float2 p3 = *(float2*)(stg + (rb + 8) * STRIDE + k0 + 8);
        split2(p0.x, p0.y, ah[mt][0], al[mt][0]);
        split2(p1.x, p1.y, ah[mt][1], al[mt][1]);
        split2(p2.x, p2.y, ah[mt][2], al[mt][2]);
        split2(p3.x, p3.y, ah[mt][3], al[mt][3]);
      }
#pragma unroll
      for (int nt = 0; nt < 8; nt++) {
        const u64 vh = sW1f[0][nt * 3 + kt][l];
        const u64 vl = sW1f[1][nt * 3 + kt][l];
        const uint32_t bh0 = (uint32_t)vh, bh1 = (uint32_t)(vh >> 32);
        const uint32_t bl0 = (uint32_t)vl, bl1 = (uint32_t)(vl >> 32);
#pragma unroll
        for (int mt = 0; mt < 2; mt++) {
          mma16816(c1[mt][nt], ah[mt], bh0, bh1);
          mma16816(c1[mt][nt], al[mt], bh0, bh1);
          mma16816(c1[mt][nt], ah[mt], bl0, bl1);
        }
      }
    }

    // ---- layer 2: C2[2m][4n] = relu(C1) @ W2 + b2 (A2 frags from C1 regs) ----
    float c2[2][4][4];
#pragma unroll
    for (int mt = 0; mt < 2; mt++)
#pragma unroll
      for (int nt = 0; nt < 4; nt++) {
        c2[mt][nt][0] = b2f[nt][0]; c2[mt][nt][1] = b2f[nt][1];
        c2[mt][nt][2] = b2f[nt][0]; c2[mt][nt][3] = b2f[nt][1];
      }
#pragma unroll
    for (int kt = 0; kt < 4; kt++) {
      uint32_t ah[2][4], al[2][4];
      const int j0 = 2 * kt, j1 = 2 * kt + 1;
#pragma unroll
      for (int mt = 0; mt < 2; mt++) {
        split2(fmaxf(c1[mt][j0][0], 0.f), fmaxf(c1[mt][j0][1], 0.f), ah[mt][0], al[mt][0]);
        split2(fmaxf(c1[mt][j0][2], 0.f), fmaxf(c1[mt][j0][3], 0.f), ah[mt][1], al[mt][1]);
        split2(fmaxf(c1[mt][j1][0], 0.f), fmaxf(c1[mt][j1][1], 0.f), ah[mt][2], al[mt][2]);
        split2(fmaxf(c1[mt][j1][2], 0.f), fmaxf(c1[mt][j1][3], 0.f), ah[mt][3], al[mt][3]);
      }
#pragma unroll
      for (int nt = 0; nt < 4; nt++)
#pragma unroll
        for (int mt = 0; mt < 2; mt++) {
          mma16816(c2[mt][nt], ah[mt], w2h[kt][nt][0], w2h[kt][nt][1]);
          mma16816(c2[mt][nt], al[mt], w2h[kt][nt][0], w2h[kt][nt][1]);
          mma16816(c2[mt][nt], ah[mt], w2l[kt][nt][0], w2l[kt][nt][1]);
        }
    }

    // ---- scatter straight from C2 fragments: red.v2, 8B per lane ----
#pragma unroll
    for (int mt = 0; mt < 2; mt++)
#pragma unroll
      for (int rh = 0; rh < 2; rh++) {
        const int el = mt * 16 + rh * 8 + lq;
        const unsigned re = __shfl_sync(0xffffffffu, row, el);
        if (eb + el < E) {
          float* p = out + (size_t)re * DO + 2 * lr;
#pragma unroll
          for (int nt = 0; nt < 4; nt++)
            red2(p + nt * 8, c2[mt][nt][rh * 2], c2[mt][nt][rh * 2 + 1]);
        }
      }
  }
}

extern "C" void kernel_launch(void* const* d_in, const int* in_sizes, int n_in,
                              void* d_out, int out_size) {
  // Identify inputs by element count; only x vs edge_index is ambiguous.
  int iW1 = 3, ib1 = 4, iW2 = 5, ib2 = 6;  // dict-order defaults
  int big[3], nbig = 0;
  for (int i = 0; i < n_in; i++) {
    int s = in_sizes[i];
    if      (s == (DN + DE) * DH) iW1 = i;
    else if (s == DH)             ib1 = i;
    else if (s == DH * DO)        iW2 = i;
    else if (s == DO)             ib2 = i;
    else if (nbig < 3)            big[nbig++] = i;
  }
  int iea = big[0];
  for (int k = 1; k < nbig; k++)
    if (in_sizes[big[k]] > in_sizes[iea]) iea = big[k];
  int cA = -1, cB = -1;
  for (int k = 0; k < nbig; k++) {
    if (big[k] == iea) continue;
    if (cA < 0) cA = big[k]; else cB = big[k];
  }

  const float* ea = (const float*)d_in[iea];
  const float* W1 = (const float*)d_in[iW1];
  const float* b1 = (const float*)d_in[ib1];
  const float* W2 = (const float*)d_in[iW2];
  const float* b2 = (const float*)d_in[ib2];
  float* out = (float*)d_out;

  int E = in_sizes[iea] / DE;   // 1,600,000
  int N = in_sizes[cA] / DN;    // 100,000

  detect<<<1, 32>>>((const unsigned*)d_in[cA], (const unsigned*)d_in[cB], (unsigned)N);
  int n4 = out_size / 4;
  zero_out<<<(n4 + 255) / 256, 256>>>((float4*)out, n4);
  edge_mma<<<296, 128>>>(d_in[cA], d_in[cB], ea, W1, b1, W2, b2, out, E,
                         (unsigned)N);
}